// round 1
// baseline (speedup 1.0000x reference)
#include <cuda_runtime.h>
#include <cuda_bf16.h>
#include <cstdint>

#define NB 16
#define C  256
#define H  128
#define W  128
#define HW (H*W)
#define KD 64          // key dim
#define TCOLS 32       // tile pixel columns
#define TP 128         // tile pixels (4 rows x 32 cols)
#define NWIN 8         // windows per tile

// ---- kernel A shared memory layout (bytes) ----
#define XB2_PITCH_W 136                 // 32-bit words per c2 row (128 pix + 8 pad)
#define XB2_BYTES  (128*XB2_PITCH_W*4)  // 69632
#define WK_PITCH   264                  // bf16 per key row (256 + 8 pad)
#define WK_BYTES   (64*WK_PITCH*2)      // 33792
#define KEY_PITCH  136                  // bf16 per key row in keybuf (aliases XB2)
#define OFF_XB2  0
#define OFF_WK   (OFF_XB2 + XB2_BYTES)
#define OFF_WS   (OFF_WK + WK_BYTES)
#define OFF_KQS  (OFF_WS + 1024)
#define OFF_WBUF (OFF_KQS + TP*4*4)
#define SMEM_A_TOTAL (OFF_WBUF + NWIN*64*4)   // 108544

// softmax weight scratch: [n][hh][ww][p(16)][s(4)]  = 1,048,576 floats (4 MB)
__device__ float g_w[NB*32*32*64];

__device__ __forceinline__ unsigned pack_bf2(float lo, float hi) {
    __nv_bfloat162 h = __floats2bfloat162_rn(lo, hi);
    return *reinterpret_cast<unsigned*>(&h);
}

// ============================================================================
// Kernel A: per tile (n, hh, 32-col chunk):
//   bf16 mma.sync GEMM key[64 x 128pix] = Wk[64x256] * x[256 x 128pix]
//   -> relu -> kq[4 x 128pix] -> per-window softmax -> weights to g_w
// ============================================================================
__global__ __launch_bounds__(256, 2) void kq_kernel(
    const float* __restrict__ x,
    const float* __restrict__ w_key,
    const float* __restrict__ w_sim)
{
    extern __shared__ char smem[];
    unsigned*       xbw    = (unsigned*)(smem + OFF_XB2);        // [c2=128][136] words, (c even, c odd) bf16 pairs
    __nv_bfloat16*  xb_bf  = (__nv_bfloat16*)(smem + OFF_XB2);
    unsigned*       wkw    = (unsigned*)(smem + OFF_WK);         // [key=64][132] words (bf16 pairs along c)
    __nv_bfloat16*  wk_bf  = (__nv_bfloat16*)(smem + OFF_WK);
    float*          ws_s   = (float*)(smem + OFF_WS);            // [4][64]
    float*          kqs    = (float*)(smem + OFF_KQS);           // [128 pix][4]
    float*          wbuf   = (float*)(smem + OFF_WBUF);          // [8 win][16 p][4 s]
    unsigned*       keyw   = (unsigned*)(smem + OFF_XB2);        // alias: keybuf [64][68] words
    __nv_bfloat16*  key_bf = (__nv_bfloat16*)(smem + OFF_XB2);   // [64][136] bf16

    const int tid  = threadIdx.x;
    const int wp   = tid >> 5;
    const int lane = tid & 31;
    const int gid  = lane >> 2;     // 0..7
    const int ctid = lane & 3;      // 0..3
    const int wchunk = blockIdx.x;  // 0..3
    const int hh     = blockIdx.y;  // 0..31
    const int n      = blockIdx.z;  // 0..15
    const int w0     = wchunk * TCOLS;

    // ---- load w_key -> bf16 smem [key][c], pitch 264 ----
    for (int i = tid; i < KD*C; i += 256) {
        int k = i >> 8, c = i & 255;
        wk_bf[k*WK_PITCH + c] = __float2bfloat16(w_key[i]);
    }
    // ---- load w_sim (4x64 = 256 floats) ----
    ws_s[tid] = w_sim[tid];

    // ---- load x tile -> interleaved bf16 pairs: word[c2][pix] = (c_even, c_odd) ----
    {
        const float* xb = x + (size_t)(n*C)*HW + (hh*4)*W + w0;
        #pragma unroll 4
        for (int i = 0; i < 32; i++) {
            int c  = wp*32 + i;
            int c2 = c >> 1, par = c & 1;
            #pragma unroll
            for (int r = 0; r < 4; r++) {
                float v = xb[(size_t)c*HW + r*W + lane];
                int pix = r*TCOLS + lane;
                xb_bf[c2*(XB2_PITCH_W*2) + pix*2 + par] = __float2bfloat16(v);
            }
        }
    }
    __syncthreads();

    // ---- GEMM: warp = (mtile 0..3, pixel-half 0..1); M=16 keys, N=64 pix, K=256 ----
    const int mtb  = (wp & 3) * 16;
    const int pixb = (wp >> 2) * 64;
    float acc[8][4];
    #pragma unroll
    for (int i = 0; i < 8; i++)
        #pragma unroll
        for (int j = 0; j < 4; j++) acc[i][j] = 0.f;

    const int arow0 = (mtb + gid) * 132;
    const int arow1 = (mtb + gid + 8) * 132;
    #pragma unroll 4
    for (int kt = 0; kt < 16; kt++) {
        unsigned a0 = wkw[arow0 + kt*8 + ctid];
        unsigned a1 = wkw[arow1 + kt*8 + ctid];
        unsigned a2 = wkw[arow0 + kt*8 + ctid + 4];
        unsigned a3 = wkw[arow1 + kt*8 + ctid + 4];
        const int b0row = (kt*8 + ctid) * XB2_PITCH_W;
        const int b1row = (kt*8 + ctid + 4) * XB2_PITCH_W;
        #pragma unroll
        for (int nt = 0; nt < 8; nt++) {
            int pix = pixb + nt*8 + gid;
            unsigned b0 = xbw[b0row + pix];
            unsigned b1 = xbw[b1row + pix];
            asm volatile(
                "mma.sync.aligned.m16n8k16.row.col.f32.bf16.bf16.f32 "
                "{%0,%1,%2,%3}, {%4,%5,%6,%7}, {%8,%9}, {%0,%1,%2,%3};"
                : "+f"(acc[nt][0]), "+f"(acc[nt][1]), "+f"(acc[nt][2]), "+f"(acc[nt][3])
                : "r"(a0), "r"(a1), "r"(a2), "r"(a3), "r"(b0), "r"(b1));
        }
    }
    __syncthreads();   // everyone done reading xb before aliasing as keybuf

    // ---- store relu(key) as bf16: keybuf[key][pix], pitch 136 (68 words) ----
    #pragma unroll
    for (int nt = 0; nt < 8; nt++) {
        int pw = (pixb >> 1) + nt*4 + ctid;   // word index of pixel pair
        keyw[(mtb + gid)     * 68 + pw] = pack_bf2(fmaxf(acc[nt][0], 0.f), fmaxf(acc[nt][1], 0.f));
        keyw[(mtb + gid + 8) * 68 + pw] = pack_bf2(fmaxf(acc[nt][2], 0.f), fmaxf(acc[nt][3], 0.f));
    }
    __syncthreads();

    // ---- kq[pix][s] = sum_k w_sim[s][k] * key[k][pix] ----
    if (tid < TP) {
        const int pix = tid;
        float kq0 = 0.f, kq1 = 0.f, kq2 = 0.f, kq3 = 0.f;
        #pragma unroll 8
        for (int k = 0; k < KD; k++) {
            float kv = __bfloat162float(key_bf[k*KEY_PITCH + pix]);
            kq0 += ws_s[k]       * kv;
            kq1 += ws_s[64 + k]  * kv;
            kq2 += ws_s[128 + k] * kv;
            kq3 += ws_s[192 + k] * kv;
        }
        kqs[pix*4 + 0] = kq0; kqs[pix*4 + 1] = kq1;
        kqs[pix*4 + 2] = kq2; kqs[pix*4 + 3] = kq3;
    }
    __syncthreads();

    // ---- per-window softmax over 16 pixels (logits / SI=4) ----
    if (tid < NWIN*4) {
        int wi = tid >> 2, s = tid & 3;
        float v[16];
        float m = -1e30f;
        #pragma unroll
        for (int r = 0; r < 4; r++)
            #pragma unroll
            for (int j = 0; j < 4; j++) {
                float t = kqs[(r*TCOLS + wi*4 + j)*4 + s] * 0.25f;
                v[r*4 + j] = t;
                m = fmaxf(m, t);
            }
        float sum = 0.f;
        #pragma unroll
        for (int p = 0; p < 16; p++) { float e = __expf(v[p] - m); v[p] = e; sum += e; }
        float inv = 1.f / sum;
        #pragma unroll
        for (int p = 0; p < 16; p++) wbuf[wi*64 + p*4 + s] = v[p] * inv;
    }
    __syncthreads();

    // ---- coalesced store of weights to global scratch ----
    const size_t base = ((size_t)((n*32 + hh)*32 + wchunk*NWIN)) * 64;
    for (int i = tid; i < NWIN*64; i += 256) g_w[base + i] = wbuf[i];
}

// ============================================================================
// Kernel B: aggregation. CTA = (hh, n) strip of 32 windows.
// lane = window; its float4 row-read is exactly its 4 window columns.
// ============================================================================
__global__ __launch_bounds__(256) void agg_kernel(
    const float* __restrict__ x, float* __restrict__ out)
{
    __shared__ float wsm[32*65];
    const int tid = threadIdx.x;
    const int hh  = blockIdx.x;
    const int n   = blockIdx.y;

    const size_t wbase = ((size_t)(n*32 + hh)) * (32*64);
    for (int i = tid; i < 2048; i += 256)
        wsm[(i >> 6)*65 + (i & 63)] = g_w[wbase + i];
    __syncthreads();

    const int wp = tid >> 5;
    const int l  = tid & 31;           // window index within the row

    float wr[16][4];
    #pragma unroll
    for (int p = 0; p < 16; p++)
        #pragma unroll
        for (int q = 0; q < 4; q++) wr[p][q] = wsm[l*65 + p*4 + q];

    for (int ci = 0; ci < 32; ci++) {
        const int c = ci*8 + wp;
        const float4* xr = (const float4*)(x + (size_t)(n*C + c)*HW + (hh*4)*W);
        float4 xv[4];
        #pragma unroll
        for (int r = 0; r < 4; r++) xv[r] = xr[r*32 + l];   // row r, cols [4l, 4l+4)

        float o0 = 0.f, o1 = 0.f, o2 = 0.f, o3 = 0.f;
        #pragma unroll
        for (int r = 0; r < 4; r++) {
            float x0 = xv[r].x, x1 = xv[r].y, x2 = xv[r].z, x3 = xv[r].w;
            o0 += x0*wr[r*4+0][0] + x1*wr[r*4+1][0] + x2*wr[r*4+2][0] + x3*wr[r*4+3][0];
            o1 += x0*wr[r*4+0][1] + x1*wr[r*4+1][1] + x2*wr[r*4+2][1] + x3*wr[r*4+3][1];
            o2 += x0*wr[r*4+0][2] + x1*wr[r*4+1][2] + x2*wr[r*4+2][2] + x3*wr[r*4+3][2];
            o3 += x0*wr[r*4+0][3] + x1*wr[r*4+1][3] + x2*wr[r*4+2][3] + x3*wr[r*4+3][3];
        }

        float2* orow = (float2*)(out + (size_t)(n*C + c)*4096 + (hh*2)*64);
        orow[l]      = make_float2(o0, o1);   // out row hh*2,   cols 2l, 2l+1
        orow[32 + l] = make_float2(o2, o3);   // out row hh*2+1
    }
}

// ============================================================================
extern "C" void kernel_launch(void* const* d_in, const int* in_sizes, int n_in,
                              void* d_out, int out_size)
{
    (void)in_sizes; (void)n_in; (void)out_size;
    const float* x  = (const float*)d_in[0];
    const float* wk = (const float*)d_in[1];
    const float* ws = (const float*)d_in[2];
    float* out = (float*)d_out;

    cudaFuncSetAttribute(kq_kernel, cudaFuncAttributeMaxDynamicSharedMemorySize,
                         SMEM_A_TOTAL);
    kq_kernel<<<dim3(4, 32, NB), 256, SMEM_A_TOTAL>>>(x, wk, ws);
    agg_kernel<<<dim3(32, NB), 256>>>(x, out);
}

// round 2
// speedup vs baseline: 1.3233x; 1.3233x over previous
#include <cuda_runtime.h>
#include <cuda_bf16.h>
#include <cstdint>

#define CC 256
#define HH 128
#define WW 128
#define HWSZ (HH*WW)
#define XP   68                    // xs pitch (floats) per channel row
#define XS_FLOATS (CC*XP)          // 17408 floats per buffer
#define KEYP 72                    // key pitch (bf16)

// shared layout (float indices)
#define SM_XS0  0
#define SM_XS1  XS_FLOATS                  // 17408
#define SM_KEY  (2*XS_FLOATS)              // 34816  (64*72 bf16 = 2304 floats)
#define SM_KQS  (SM_KEY + (64*KEYP)/2)     // 37120  (64 pix * 4 s)
#define SM_WBUF (SM_KQS + 256)             // 37376  (4 win * 68)
#define SM_WSS  (SM_WBUF + 272)            // 37648  (4*64 w_sim)
#define SMEM_FLOATS (SM_WSS + 256)         // 37904
#define SMEM_BYTES (SMEM_FLOATS*4)         // 151616

__device__ __forceinline__ unsigned pack_bf2(float lo, float hi) {
    __nv_bfloat162 h = __floats2bfloat162_rn(lo, hi);
    return *reinterpret_cast<unsigned*>(&h);
}

__global__ __launch_bounds__(512, 1) void frac_fused_kernel(
    const float* __restrict__ x,
    const float* __restrict__ w_key,
    const float* __restrict__ w_sim,
    float* __restrict__ out)
{
    extern __shared__ float S[];
    __nv_bfloat16* key  = (__nv_bfloat16*)(S + SM_KEY);
    unsigned*      keyw = (unsigned*)(S + SM_KEY);       // [64][36] words
    float*         kqs  = S + SM_KQS;                    // [64 pix][4 s]
    float*         wbuf = S + SM_WBUF;                   // [4 win][68]
    float*         wss  = S + SM_WSS;                    // [4][64]
    unsigned*      wkst = (unsigned*)(S + SM_XS1);       // prologue only: [64][132] bf16-pair words

    const int tid  = threadIdx.x;
    const int wp   = tid >> 5;
    const int lane = tid & 31;
    const int gid  = lane >> 2;        // 0..7
    const int ctid = lane & 3;         // 0..3
    const int mtb  = (wp & 3) * 16;    // key-row tile base
    const int pixb = (wp >> 2) * 16;   // pixel tile base (pq*16)
    const int wh = blockIdx.x;         // 0..1  (64-col half)
    const int hh = blockIdx.y;         // 0..31
    const int n  = blockIdx.z;         // 0..15

    const uint32_t sbase = (uint32_t)__cvta_generic_to_shared(S);
    const float* xbase = x + ((size_t)n*CC)*HWSZ + (size_t)(hh*4)*WW + wh*64;

    // ---- prefetch chunk 0 into buf0 ----
    {
        const float* src = xbase;
        #pragma unroll
        for (int i = 0; i < 8; i++) {
            int id = i*512 + tid;                  // 0..4095 16B units
            int c = id >> 4, r = (id >> 2) & 3, u = id & 3;
            const float* g = src + (size_t)c*HWSZ + r*WW + u*4;
            uint32_t d = sbase + (uint32_t)((c*XP + r*16 + u*4) * 4);
            asm volatile("cp.async.cg.shared.global [%0], [%1], 16;" :: "r"(d), "l"(g));
        }
        asm volatile("cp.async.commit_group;");
    }

    // ---- stage w_key as bf16 pairs into buf1 region (prologue only) ----
    for (int i = tid; i < 64*128; i += 512) {
        int k = i >> 7, c2 = i & 127;
        float2 v = *(const float2*)(w_key + k*256 + c2*2);
        wkst[k*132 + c2] = pack_bf2(v.x, v.y);
    }
    if (tid < 256) wss[tid] = w_sim[tid];
    __syncthreads();

    // ---- A fragments (w_key) to registers, persistent across chunks ----
    unsigned a[16][4];
    #pragma unroll
    for (int kt = 0; kt < 16; kt++) {
        a[kt][0] = wkst[(mtb+gid)  *132 + kt*8 + ctid];
        a[kt][1] = wkst[(mtb+gid+8)*132 + kt*8 + ctid];
        a[kt][2] = wkst[(mtb+gid)  *132 + kt*8 + ctid + 4];
        a[kt][3] = wkst[(mtb+gid+8)*132 + kt*8 + ctid + 4];
    }
    __syncthreads();   // all A reads done before buf1 gets chunk 1

    for (int ch = 0; ch < 4; ch++) {
        __syncthreads();                         // prev chunk fully consumed
        if (ch < 3) {                            // prefetch next chunk
            const float* src = xbase + (ch+1)*16;
            uint32_t dst0 = sbase + (((ch+1)&1) ? (uint32_t)(SM_XS1*4) : 0u);
            #pragma unroll
            for (int i = 0; i < 8; i++) {
                int id = i*512 + tid;
                int c = id >> 4, r = (id >> 2) & 3, u = id & 3;
                const float* g = src + (size_t)c*HWSZ + r*WW + u*4;
                uint32_t d = dst0 + (uint32_t)((c*XP + r*16 + u*4) * 4);
                asm volatile("cp.async.cg.shared.global [%0], [%1], 16;" :: "r"(d), "l"(g));
            }
            asm volatile("cp.async.commit_group;");
            asm volatile("cp.async.wait_group 1;");
        } else {
            asm volatile("cp.async.wait_group 0;");
        }
        __syncthreads();                         // current chunk visible

        const float* Xs = S + ((ch & 1) ? SM_XS1 : 0);

        // ---- GEMM: key[64 x 64pix] = Wk * x, bf16 mma.sync, fp32 acc ----
        float acc[2][4] = {{0.f,0.f,0.f,0.f},{0.f,0.f,0.f,0.f}};
        #pragma unroll
        for (int kt = 0; kt < 16; kt++) {
            const float* xc = Xs + (kt*16 + 2*ctid)*XP;
            #pragma unroll
            for (int nt = 0; nt < 2; nt++) {
                int pix = pixb + nt*8 + gid;
                unsigned b0 = pack_bf2(xc[pix],        xc[XP   + pix]);
                unsigned b1 = pack_bf2(xc[8*XP + pix], xc[9*XP + pix]);
                asm volatile(
                    "mma.sync.aligned.m16n8k16.row.col.f32.bf16.bf16.f32 "
                    "{%0,%1,%2,%3}, {%4,%5,%6,%7}, {%8,%9}, {%0,%1,%2,%3};"
                    : "+f"(acc[nt][0]), "+f"(acc[nt][1]), "+f"(acc[nt][2]), "+f"(acc[nt][3])
                    : "r"(a[kt][0]), "r"(a[kt][1]), "r"(a[kt][2]), "r"(a[kt][3]),
                      "r"(b0), "r"(b1));
            }
        }
        // relu(key) -> smem bf16 [key][pix]
        #pragma unroll
        for (int nt = 0; nt < 2; nt++) {
            int pw = (pixb >> 1) + nt*4 + ctid;     // pixel-pair word index
            keyw[(mtb+gid)  *36 + pw] = pack_bf2(fmaxf(acc[nt][0],0.f), fmaxf(acc[nt][1],0.f));
            keyw[(mtb+gid+8)*36 + pw] = pack_bf2(fmaxf(acc[nt][2],0.f), fmaxf(acc[nt][3],0.f));
        }
        __syncthreads();

        // ---- kq[pix][s] = sum_k w_sim[s][k] * key[k][pix] ----
        if (tid < 256) {
            int pix = tid >> 2, s = tid & 3;
            float kq = 0.f;
            #pragma unroll 8
            for (int k = 0; k < 64; k++)
                kq += wss[s*64 + k] * __bfloat162float(key[k*KEYP + pix]);
            kqs[tid] = kq;
        }
        __syncthreads();

        // ---- per-window softmax over 16 pixels (logits / 4) ----
        if (tid < 16) {
            int win = tid >> 2, s = tid & 3;
            float v[16], m = -1e30f;
            #pragma unroll
            for (int r0 = 0; r0 < 4; r0++)
                #pragma unroll
                for (int j = 0; j < 4; j++) {
                    float t = kqs[(r0*16 + win*4 + j)*4 + s] * 0.25f;
                    v[r0*4+j] = t;
                    m = fmaxf(m, t);
                }
            float sum = 0.f;
            #pragma unroll
            for (int p = 0; p < 16; p++) { float e = __expf(v[p]-m); v[p] = e; sum += e; }
            float inv = 1.f / sum;
            #pragma unroll
            for (int p = 0; p < 16; p++) wbuf[win*68 + p*4 + s] = v[p]*inv;
        }
        __syncthreads();

        // ---- aggregation from fp32 smem x, direct coalesced float2 stores ----
        {
            const int sp   = tid & 1;           // output row within window (rr)
            const int win  = (tid >> 1) & 3;    // window within chunk
            const int crow = tid >> 3;          // 0..63
            float2 w2[16];
            #pragma unroll
            for (int p = 0; p < 16; p++)
                w2[p] = *(const float2*)(wbuf + win*68 + p*4 + 2*sp);
            const int ww = wh*16 + ch*4 + win;
            #pragma unroll
            for (int cg = 0; cg < 4; cg++) {
                int c = cg*64 + crow;
                const float* xc = Xs + c*XP + win*4;
                float o0 = 0.f, o1 = 0.f;
                #pragma unroll
                for (int r0 = 0; r0 < 4; r0++) {
                    float4 xv = *(const float4*)(xc + r0*16);
                    o0 += xv.x*w2[r0*4+0].x + xv.y*w2[r0*4+1].x
                        + xv.z*w2[r0*4+2].x + xv.w*w2[r0*4+3].x;
                    o1 += xv.x*w2[r0*4+0].y + xv.y*w2[r0*4+1].y
                        + xv.z*w2[r0*4+2].y + xv.w*w2[r0*4+3].y;
                }
                float2* op = (float2*)(out + ((size_t)(n*CC + c)*64 + (2*hh+sp))*64 + 2*ww);
                *op = make_float2(o0, o1);
            }
        }
    }
}

extern "C" void kernel_launch(void* const* d_in, const int* in_sizes, int n_in,
                              void* d_out, int out_size)
{
    (void)in_sizes; (void)n_in; (void)out_size;
    const float* x  = (const float*)d_in[0];
    const float* wk = (const float*)d_in[1];
    const float* ws = (const float*)d_in[2];
    float* out = (float*)d_out;

    cudaFuncSetAttribute(frac_fused_kernel,
                         cudaFuncAttributeMaxDynamicSharedMemorySize, SMEM_BYTES);
    frac_fused_kernel<<<dim3(2, 32, 16), 512, SMEM_BYTES>>>(x, wk, ws, out);
}